// round 9
// baseline (speedup 1.0000x reference)
#include <cuda_runtime.h>
#include <cuda_bf16.h>
#include <cstdint>

#define LMAX 8
#define TPB 128
// Buffer holds sections l=1..8: sum(2l+1) = 80 floats/point -> 40,960 B.
#define BUF_FLOATS (TPB * 80)

// ---------------------------------------------------------------------------
// Compile-time constants (constexpr Newton sqrt -> SASS immediates).
// ---------------------------------------------------------------------------
__host__ __device__ constexpr double cfact(int n) {
    double r = 1.0;
    for (int i = 2; i <= n; ++i) r *= (double)i;
    return r;
}
__host__ __device__ constexpr double csqrt_(double x) {
    double g = x < 1.0 ? 1.0 : x;
    for (int i = 0; i < 100; ++i) g = 0.5 * (g + x / g);
    return g;
}
constexpr double PI_D = 3.141592653589793238462643383279502884;

__host__ __device__ constexpr float Fcoef(int l, int m) {
    double v = csqrt_(((2.0 * l + 1.0) / (2.0 * PI_D)) * (cfact(l - m) / cfact(l + m)));
    return (float)((m & 1) ? -v : v);
}
__host__ __device__ constexpr float Acoef(int l) {
    return (float)csqrt_((2.0 * l + 1.0) / (4.0 * PI_D));
}

// ---------------------------------------------------------------------------
// PTX wrappers
// ---------------------------------------------------------------------------
__device__ __forceinline__ uint32_t smem_u32(const void* p) {
    uint32_t a;
    asm("{ .reg .u64 t; cvta.to.shared.u64 t, %1; cvt.u32.u64 %0, t; }"
        : "=r"(a) : "l"(p));
    return a;
}
__device__ __forceinline__ void bulk_store(void* gdst, uint32_t ssrc, uint32_t bytes) {
    asm volatile("cp.async.bulk.global.shared::cta.bulk_group [%0], [%1], %2;"
                 :: "l"(gdst), "r"(ssrc), "r"(bytes) : "memory");
}

// ---------------------------------------------------------------------------
// Emit section L into the tile. Section l starts at float offset TPB*(l*l-1)
// (prefix sum of 2k+1, k=1..l-1). Point row at tid*(2L+1): odd stride ->
// bank-conflict-free STS.
// ---------------------------------------------------------------------------
template<int L, int M>
__device__ __forceinline__ void emit_ms(float* __restrict__ o,
                                        const float (&Q)[LMAX + 1][LMAX + 1],
                                        const float (&s)[LMAX + 1],
                                        const float (&c)[LMAX + 1]) {
    if constexpr (M >= 1) {
        constexpr float f = Fcoef(L, M);
        float fq = f * Q[L][M];
        o[L - M] = fq * s[M];
        o[L + M] = fq * c[M];
        emit_ms<L, M - 1>(o, Q, s, c);
    }
}

template<int L>
__device__ __forceinline__ void emit_sec(float* __restrict__ tile, int tid,
                                         const float (&Q)[LMAX + 1][LMAX + 1],
                                         const float (&s)[LMAX + 1],
                                         const float (&c)[LMAX + 1]) {
    float* o = tile + TPB * (L * L - 1) + tid * (2 * L + 1);
    constexpr float a = Acoef(L);
    o[L] = a * Q[L][0];
    emit_ms<L, L>(o, Q, s, c);
}

// ---------------------------------------------------------------------------
// Kernel: compute -> conflict-free STS -> one barrier -> TMA bulk drain.
// ---------------------------------------------------------------------------
__global__ void __launch_bounds__(TPB)
solid_harmonics_kernel(const float* __restrict__ R, float* __restrict__ out, int N) {
    __shared__ __align__(16) float tile[BUF_FLOATS];

    const int tid = threadIdx.x;
    const long long n0 = (long long)blockIdx.x * TPB;
    const long long n = n0 + tid;
    const int P = (int)min((long long)TPB, (long long)N - n0);
    const long long NN = N;
    const bool valid = (n < (long long)N);
    // TMA path requires 16B alignment of every src/dst: N%4==0 && P%4==0.
    const bool use_tma = ((N & 3) == 0) && ((P & 3) == 0);

    if (valid) {
        float x = R[3 * n + 0];
        float y = R[3 * n + 1];
        float z = R[3 * n + 2];
        float r2 = x * x + y * y + z * z;

        float c[LMAX + 1], s[LMAX + 1];
        c[0] = 1.0f;
        s[0] = 0.0f;
#pragma unroll
        for (int m = 1; m <= LMAX; ++m) {
            c[m] = x * c[m - 1] - y * s[m - 1];
            s[m] = x * s[m - 1] + y * c[m - 1];
        }

        float Q[LMAX + 1][LMAX + 1];
        Q[0][0] = 1.0f;
#pragma unroll
        for (int l = 1; l <= LMAX; ++l) {
            Q[l][l] = (float)(-(2 * l - 1)) * Q[l - 1][l - 1];
            Q[l][l - 1] = (float)(2 * l - 1) * z * Q[l - 1][l - 1];
#pragma unroll
            for (int m = l - 2; m >= 0; --m) {
                Q[l][m] = ((float)(2 * l - 1) * z * Q[l - 1][m]
                           - (float)(l + m - 1) * r2 * Q[l - 2][m])
                          * (1.0f / (float)(l - m));
            }
        }

        // l = 0 is a constant: direct coalesced store, no staging.
        out[n] = Acoef(0);

        emit_sec<1>(tile, tid, Q, s, c);
        emit_sec<2>(tile, tid, Q, s, c);
        emit_sec<3>(tile, tid, Q, s, c);
        emit_sec<4>(tile, tid, Q, s, c);
        emit_sec<5>(tile, tid, Q, s, c);
        emit_sec<6>(tile, tid, Q, s, c);
        emit_sec<7>(tile, tid, Q, s, c);
        emit_sec<8>(tile, tid, Q, s, c);
    }

    __syncthreads();

    if (use_tma) {
        if (tid == 0) {
            // Order generic-proxy STS writes before async-proxy TMA reads.
            asm volatile("fence.proxy.async.shared::cta;" ::: "memory");
            const uint32_t sbase = smem_u32(tile);
#pragma unroll
            for (int l = 1; l <= LMAX; ++l) {
                const int w = 2 * l + 1;
                float* dst = out + (long long)(l * l) * NN + n0 * w;
                const uint32_t src = sbase + (uint32_t)(TPB * (l * l - 1)) * 4u;
                bulk_store(dst, src, (uint32_t)(P * w * 4));
            }
            asm volatile("cp.async.bulk.commit_group;" ::: "memory");
            // Keep this thread (and thus the CTA's smem) alive until the TMA
            // engine has finished reading the tile.
            asm volatile("cp.async.bulk.wait_group 0;" ::: "memory");
        }
    } else {
        // Fallback: coalesced scalar copy of the valid prefix of each section.
#pragma unroll
        for (int l = 1; l <= LMAX; ++l) {
            const int w = 2 * l + 1;
            const float* src = tile + TPB * (l * l - 1);
            float* dst = out + (long long)(l * l) * NN + n0 * w;
            const int cnt = P * w;
            for (int j = tid; j < cnt; j += TPB) dst[j] = src[j];
        }
    }
}

extern "C" void kernel_launch(void* const* d_in, const int* in_sizes, int n_in,
                              void* d_out, int out_size) {
    const float* R = (const float*)d_in[0];
    float* out = (float*)d_out;
    int N = in_sizes[0] / 3;

    int blocks = (N + TPB - 1) / TPB;
    solid_harmonics_kernel<<<blocks, TPB>>>(R, out, N);
}